// round 3
// baseline (speedup 1.0000x reference)
#include <cuda_runtime.h>
#include <math.h>

#define LSEQ 512
#define BATCH 2
#define DG 256
#define DB 128
#define NH 8
#define HD 32
#define BH (BATCH*NH)   // 16

// ---------------- scratch (device globals; no allocation allowed) ----------------
__device__ float g_xn[BATCH*LSEQ*DG];        // LN(x)                [1024][256]
__device__ float g_q[BH*LSEQ*HD];            // [b*h][l][32]
__device__ float g_k[BH*LSEQ*HD];            // pre-scaled by 1/sqrt(32)
__device__ float g_v[BH*LSEQ*HD];
__device__ float g_gate[BATCH*LSEQ*DG];      // sigmoid(xn@Wg+bg)    [1024][256]
__device__ float g_pb[(size_t)BH*LSEQ*LSEQ]; // pair bias            [b*h][q][k]
__device__ float g_hid[BATCH*LSEQ*DG];       // gate * attn_out      [1024][256]
__device__ float g_wgt[NH*DB];               // b_gamma[i]*Wb[i][h]  [h][i]
__device__ float g_cw[NH];                   // sum_i b_gamma[i]*Wb[i][h]
__device__ float g_bb[NH];                   // b_beta @ Wb[:,h]

// ---------------- prep: fold b_gamma/b_beta into Wb ----------------
__global__ void prep_wb(const float* __restrict__ b_gamma,
                        const float* __restrict__ b_beta,
                        const float* __restrict__ Wb) {
    __shared__ float sc[NH][DB];
    __shared__ float sb[NH][DB];
    int i = threadIdx.x;            // 128 threads
    float g = b_gamma[i];
    float bt = b_beta[i];
#pragma unroll
    for (int h = 0; h < NH; h++) {
        float w = Wb[i*NH + h];
        g_wgt[h*DB + i] = g * w;
        sc[h][i] = g * w;
        sb[h][i] = bt * w;
    }
    __syncthreads();
    if (i < NH) {
        float a = 0.f, b2 = 0.f;
        for (int j = 0; j < DB; j++) { a += sc[i][j]; b2 += sb[i][j]; }
        g_cw[i] = a;
        g_bb[i] = b2;
    }
}

// ---------------- LN over x rows (dim 256), warp per row ----------------
__global__ void __launch_bounds__(128) ln_x(const float* __restrict__ x,
                                            const float* __restrict__ gamma,
                                            const float* __restrict__ beta) {
    int warp = threadIdx.x >> 5, lane = threadIdx.x & 31;
    int row = blockIdx.x * 4 + warp;           // 1024 rows, grid 256
    const float* rp = x + (size_t)row * DG;
    float4 v0 = *(const float4*)(rp + lane*4);
    float4 v1 = *(const float4*)(rp + 128 + lane*4);
    float s1 = v0.x+v0.y+v0.z+v0.w + v1.x+v1.y+v1.z+v1.w;
    float s2 = v0.x*v0.x+v0.y*v0.y+v0.z*v0.z+v0.w*v0.w
             + v1.x*v1.x+v1.y*v1.y+v1.z*v1.z+v1.w*v1.w;
#pragma unroll
    for (int off = 16; off; off >>= 1) {
        s1 += __shfl_xor_sync(0xffffffffu, s1, off);
        s2 += __shfl_xor_sync(0xffffffffu, s2, off);
    }
    float mu = s1 * (1.f/256.f);
    float var = s2 * (1.f/256.f) - mu*mu;
    float rstd = rsqrtf(var + 1e-5f);
    float4 gm0 = *(const float4*)(gamma + lane*4);
    float4 gm1 = *(const float4*)(gamma + 128 + lane*4);
    float4 bt0 = *(const float4*)(beta + lane*4);
    float4 bt1 = *(const float4*)(beta + 128 + lane*4);
    float4 o0, o1;
    o0.x = (v0.x-mu)*rstd*gm0.x + bt0.x; o0.y = (v0.y-mu)*rstd*gm0.y + bt0.y;
    o0.z = (v0.z-mu)*rstd*gm0.z + bt0.z; o0.w = (v0.w-mu)*rstd*gm0.w + bt0.w;
    o1.x = (v1.x-mu)*rstd*gm1.x + bt1.x; o1.y = (v1.y-mu)*rstd*gm1.y + bt1.y;
    o1.z = (v1.z-mu)*rstd*gm1.z + bt1.z; o1.w = (v1.w-mu)*rstd*gm1.w + bt1.w;
    *(float4*)(g_xn + (size_t)row*DG + lane*4) = o0;
    *(float4*)(g_xn + (size_t)row*DG + 128 + lane*4) = o1;
}

// ---------------- fused GEMM: xn @ [Wq|Wk|Wv|Wg] (M=1024, N=1024, K=256) ----------------
__global__ void __launch_bounds__(256) gemm_qkvg(const float* __restrict__ Wq,
                                                 const float* __restrict__ Wk,
                                                 const float* __restrict__ Wv,
                                                 const float* __restrict__ Wg,
                                                 const float* __restrict__ bg) {
    __shared__ __align__(16) float Ast[16*68];   // [k][m] transposed, padded
    __shared__ __align__(16) float Bs [16*68];   // [k][n], padded
    int tid = threadIdx.x;
    int bm = blockIdx.y * 64;
    int bn_g = blockIdx.x * 64;          // 0..1023
    int which = bn_g >> 8;               // 0:Q 1:K 2:V 3:G
    int bn = bn_g & 255;
    const float* W = (which==0) ? Wq : (which==1) ? Wk : (which==2) ? Wv : Wg;
    int ty = tid >> 4, tx = tid & 15;
    int ar = tid >> 2, ac4 = tid & 3;
    int br = tid >> 4, bc4 = tid & 15;
    float acc[4][4] = {};
    for (int kb = 0; kb < 256; kb += 16) {
        float4 av = *(const float4*)(g_xn + (size_t)(bm+ar)*256 + kb + ac4*4);
        Ast[(ac4*4+0)*68 + ar] = av.x;
        Ast[(ac4*4+1)*68 + ar] = av.y;
        Ast[(ac4*4+2)*68 + ar] = av.z;
        Ast[(ac4*4+3)*68 + ar] = av.w;
        *(float4*)&Bs[br*68 + bc4*4] = *(const float4*)(W + (size_t)(kb+br)*256 + bn + bc4*4);
        __syncthreads();
#pragma unroll
        for (int k = 0; k < 16; k++) {
            float4 a = *(float4*)&Ast[k*68 + ty*4];
            float4 b = *(float4*)&Bs [k*68 + tx*4];
            acc[0][0]=fmaf(a.x,b.x,acc[0][0]); acc[0][1]=fmaf(a.x,b.y,acc[0][1]);
            acc[0][2]=fmaf(a.x,b.z,acc[0][2]); acc[0][3]=fmaf(a.x,b.w,acc[0][3]);
            acc[1][0]=fmaf(a.y,b.x,acc[1][0]); acc[1][1]=fmaf(a.y,b.y,acc[1][1]);
            acc[1][2]=fmaf(a.y,b.z,acc[1][2]); acc[1][3]=fmaf(a.y,b.w,acc[1][3]);
            acc[2][0]=fmaf(a.z,b.x,acc[2][0]); acc[2][1]=fmaf(a.z,b.y,acc[2][1]);
            acc[2][2]=fmaf(a.z,b.z,acc[2][2]); acc[2][3]=fmaf(a.z,b.w,acc[2][3]);
            acc[3][0]=fmaf(a.w,b.x,acc[3][0]); acc[3][1]=fmaf(a.w,b.y,acc[3][1]);
            acc[3][2]=fmaf(a.w,b.z,acc[3][2]); acc[3][3]=fmaf(a.w,b.w,acc[3][3]);
        }
        __syncthreads();
    }
    const float kscale = 0.17677669529663687f; // 1/sqrt(32)
#pragma unroll
    for (int i = 0; i < 4; i++) {
#pragma unroll
        for (int j = 0; j < 4; j++) {
            int m = bm + ty*4 + i;
            int n = bn + tx*4 + j;
            float v = acc[i][j];
            if (which < 3) {
                if (which == 1) v *= kscale;
                int b = m >> 9, pos = m & 511, h = n >> 5, d = n & 31;
                float* dst = (which==0) ? g_q : (which==1) ? g_k : g_v;
                dst[((size_t)(b*NH + h)*LSEQ + pos)*HD + d] = v;
            } else {
                v = 1.f / (1.f + __expf(-(v + bg[n])));
                g_gate[(size_t)m*DG + n] = v;
            }
        }
    }
}

// ---------------- fused LN(bias) @ Wb -> pair bias in [b,h,q,k] ----------------
// 8 lanes per row (16 elems/lane), 10 simultaneous reductions (sum, sumsq, 8 dots)
__global__ void __launch_bounds__(256) pair_ln(const float* __restrict__ bias) {
    __shared__ __align__(16) float swg[NH*DB];
    __shared__ float scw[NH], sbb[NH];
    int tid = threadIdx.x;
    for (int i = tid; i < NH*DB; i += 256) swg[i] = g_wgt[i];
    if (tid < NH) { scw[tid] = g_cw[tid]; sbb[tid] = g_bb[tid]; }
    __syncthreads();
    int warp = tid >> 5, lane = tid & 31;
    int sub = lane >> 3, li = lane & 7;
    unsigned row = blockIdx.x * 32u + warp * 4u + sub;   // < 524288
    const float* rp = bias + (size_t)row * DB + li * 16;
    float s1 = 0.f, s2 = 0.f;
    float d[8] = {0,0,0,0,0,0,0,0};
#pragma unroll
    for (int j = 0; j < 4; j++) {
        float4 v = *(const float4*)(rp + j*4);
        s1 += v.x + v.y + v.z + v.w;
        s2 = fmaf(v.x,v.x, fmaf(v.y,v.y, fmaf(v.z,v.z, fmaf(v.w,v.w, s2))));
#pragma unroll
        for (int h = 0; h < 8; h++) {
            float4 w = *(const float4*)&swg[h*DB + li*16 + j*4];
            d[h] = fmaf(v.x,w.x, fmaf(v.y,w.y, fmaf(v.z,w.z, fmaf(v.w,w.w, d[h]))));
        }
    }
#pragma unroll
    for (int off = 4; off; off >>= 1) {
        s1 += __shfl_xor_sync(0xffffffffu, s1, off);
        s2 += __shfl_xor_sync(0xffffffffu, s2, off);
#pragma unroll
        for (int h = 0; h < 8; h++) d[h] += __shfl_xor_sync(0xffffffffu, d[h], off);
    }
    float mu = s1 * (1.f/128.f);
    float var = s2 * (1.f/128.f) - mu*mu;
    float rstd = rsqrtf(var + 1e-5f);
    int h = li;
    float val = fmaf(rstd, d[h] - mu*scw[h], sbb[h]);
    unsigned b = row >> 18, q = (row >> 9) & 511u, k = row & 511u;
    g_pb[(((size_t)(b*NH + h)*LSEQ + q))*LSEQ + k] = val;
}

// ---------------- flash-style attention + gate ----------------
// block: 128 threads, 32 q rows; thread = (ty 0..15: 2 q rows, tx 0..7: k lanes / 4 d cols)
__global__ void __launch_bounds__(128) attn_kernel() {
    __shared__ __align__(16) float Qs[32*36];
    __shared__ __align__(16) float Ks[64*36];
    __shared__ __align__(16) float Vs[64*32];
    __shared__ __align__(16) float Ps[32*64];
    int tid = threadIdx.x;
    int bh = blockIdx.x >> 4;
    int q0 = (blockIdx.x & 15) * 32;
    const float* Qg = g_q + (size_t)bh * LSEQ * HD;
    const float* Kg = g_k + (size_t)bh * LSEQ * HD;
    const float* Vg = g_v + (size_t)bh * LSEQ * HD;
    for (int i = tid; i < 256; i += 128) {
        int r = i >> 3, c = i & 7;
        *(float4*)&Qs[r*36 + c*4] = *(const float4*)(Qg + (size_t)(q0+r)*HD + c*4);
    }
    int ty = tid >> 3, tx = tid & 7;
    int qa = q0 + 2*ty;
    const float* pb0 = g_pb + ((size_t)bh * LSEQ + qa) * LSEQ;
    const float* pb1 = pb0 + LSEQ;
    float m0 = __int_as_float(0xff800000u), m1 = m0;
    float l0 = 0.f, l1 = 0.f;
    float c0[4] = {0,0,0,0}, c1[4] = {0,0,0,0};

    for (int kt = 0; kt < LSEQ; kt += 64) {
        __syncthreads();
        for (int i = tid; i < 512; i += 128) {
            int r = i >> 3, c = i & 7;
            *(float4*)&Ks[r*36 + c*4] = *(const float4*)(Kg + (size_t)(kt+r)*HD + c*4);
        }
        for (int i = tid; i < 512; i += 128) {
            int r = i >> 3, c = i & 7;
            *(float4*)&Vs[r*32 + c*4] = *(const float4*)(Vg + (size_t)(kt+r)*HD + c*4);
        }
        __syncthreads();
        // logits: s[j] for k = kt + tx + 8j  (interleaved -> conflict-free Ks reads)
        float s0[8], s1v[8];
#pragma unroll
        for (int j = 0; j < 8; j++) {
            s0[j]  = pb0[kt + tx + 8*j];
            s1v[j] = pb1[kt + tx + 8*j];
        }
#pragma unroll
        for (int d4 = 0; d4 < 8; d4++) {
            float4 a0 = *(float4*)&Qs[(2*ty  )*36 + d4*4];
            float4 a1 = *(float4*)&Qs[(2*ty+1)*36 + d4*4];
#pragma unroll
            for (int j = 0; j < 8; j++) {
                float4 kv = *(float4*)&Ks[(tx + 8*j)*36 + d4*4];
                s0[j]  = fmaf(a0.x,kv.x, fmaf(a0.y,kv.y, fmaf(a0.z,kv.z, fmaf(a0.w,kv.w, s0[j]))));
                s1v[j] = fmaf(a1.x,kv.x, fmaf(a1.y,kv.y, fmaf(a1.z,kv.z, fmaf(a1.w,kv.w, s1v[j]))));
            }
        }
        // online softmax across the 8-lane group
        float mx0 = s0[0], mx1 = s1v[0];
#pragma unroll
        for (int j = 1; j < 8; j++) { mx0 = fmaxf(mx0, s0[j]); mx1 = fmaxf(mx1, s1v[j]); }
#pragma unroll
        for (int off = 4; off; off >>= 1) {
            mx0 = fmaxf(mx0, __shfl_xor_sync(0xffffffffu, mx0, off));
            mx1 = fmaxf(mx1, __shfl_xor_sync(0xffffffffu, mx1, off));
        }
        float mn0 = fmaxf(m0, mx0), mn1 = fmaxf(m1, mx1);
        float sc0 = __expf(m0 - mn0), sc1 = __expf(m1 - mn1);
        float sum0 = 0.f, sum1 = 0.f;
#pragma unroll
        for (int j = 0; j < 8; j++) {
            s0[j]  = __expf(s0[j]  - mn0); sum0 += s0[j];
            s1v[j] = __expf(s1v[j] - mn1); sum1 += s1v[j];
        }
#pragma unroll
        for (int off = 4; off; off >>= 1) {
            sum0 += __shfl_xor_sync(0xffffffffu, sum0, off);
            sum1 += __shfl_xor_sync(0xffffffffu, sum1, off);
        }
        l0 = l0*sc0 + sum0; l1 = l1*sc1 + sum1;
        m0 = mn0; m1 = mn1;
#pragma unroll
        for (int j = 0; j < 4; j++) { c0[j] *= sc0; c1[j] *= sc1; }
#pragma unroll
        for (int j = 0; j < 8; j++) {
            Ps[(2*ty  )*64 + tx + 8*j] = s0[j];
            Ps[(2*ty+1)*64 + tx + 8*j] = s1v[j];
        }
        __syncthreads();
        // O += P @ V  (thread: 2 q rows x 4 d cols, d = tx*4..+3)
#pragma unroll
        for (int k4 = 0; k4 < 16; k4++) {
            float4 pa = *(float4*)&Ps[(2*ty  )*64 + k4*4];
            float4 pb_ = *(float4*)&Ps[(2*ty+1)*64 + k4*4];
            float4 va = *(float4*)&Vs[(k4*4+0)*32 + tx*4];
            float4 vb = *(float4*)&Vs[(k4*4+1)*32 + tx*4];
            float4 vc = *(float4*)&Vs[(k4*4+2)*32 + tx*4];
            float4 vd = *(float4*)&Vs[(k4*4+3)*32 + tx*4];
            c0[0]=fmaf(pa.x,va.x,c0[0]); c0[1]=fmaf(pa.x,va.y,c0[1]); c0[2]=fmaf(pa.x,va.z,c0[2]); c0[3]=fmaf(pa.x,va.w,c0[3]);
            c1[0]=fmaf(pb_.x,va.x,c1[0]); c1[1]=fmaf(pb_.x,va.y,c1[1]); c1[2]=fmaf(pb_.x,va.z,c1[2]); c1[3]=fmaf(pb_.x,va.w,c1[3]);
            c0[0]=fmaf(pa.y,vb.x,c0[0]); c0[1]=fmaf(pa.y,vb.y,c0[1]); c0[2]=fmaf(pa.y,vb.z,c0[2]); c0[3]=fmaf(pa.y,vb.w,c0[3]);
            c1[0]=fmaf(pb_.y,vb.x,c1[0]); c1[1]=fmaf(pb_.y,vb.y,c1[1]); c1[2]=fmaf(pb_.y,vb.z,c1[2]); c1[3]=fmaf(pb_.y,vb.w,c1[3]);
            c0[0]=fmaf(pa.z,vc.x,c0[0]); c0[1]=fmaf(pa.z,vc.y,c0[1]); c0[2]=fmaf(pa.z,vc.z,c0[2]); c0[3]=fmaf(pa.z,vc.w,c0[3]);
            c1[0]=fmaf(pb_.z,vc.x,c1[0]); c1[1]=fmaf(pb_.z,vc.y,c1[1]); c1[2]=fmaf(pb_.z,vc.z,c1[2]); c1[3]=fmaf(pb_.z,vc.w,c1[3]);
            c0[0]=fmaf(pa.w,vd.x,c0[0]); c0[1]=fmaf(pa.w,vd.y,c0[1]); c0[2]=fmaf(pa.w,vd.z,c0[2]); c0[3]=fmaf(pa.w,vd.w,c0[3]);
            c1[0]=fmaf(pb_.w,vd.x,c1[0]); c1[1]=fmaf(pb_.w,vd.y,c1[1]); c1[2]=fmaf(pb_.w,vd.z,c1[2]); c1[3]=fmaf(pb_.w,vd.w,c1[3]);
        }
    }
    float inv0 = 1.f / l0, inv1 = 1.f / l1;
    int b = bh >> 3, h = bh & 7;
    int mrow = b * LSEQ + qa;
    const float* gt = g_gate + (size_t)mrow * DG + h*HD + tx*4;
    float4 gA = *(const float4*)gt;
    float4 gB = *(const float4*)(gt + DG);
    float4 oA = make_float4(c0[0]*inv0*gA.x, c0[1]*inv0*gA.y, c0[2]*inv0*gA.z, c0[3]*inv0*gA.w);
    float4 oB = make_float4(c1[0]*inv1*gB.x, c1[1]*inv1*gB.y, c1[2]*inv1*gB.z, c1[3]*inv1*gB.w);
    *(float4*)(g_hid + (size_t)mrow*DG + h*HD + tx*4) = oA;
    *(float4*)(g_hid + (size_t)(mrow+1)*DG + h*HD + tx*4) = oB;
}

// ---------------- final GEMM: hid @ Wout + bout ----------------
__global__ void __launch_bounds__(256) gemm_out(const float* __restrict__ Wout,
                                                const float* __restrict__ bout,
                                                float* __restrict__ out) {
    __shared__ __align__(16) float Ast[16*68];
    __shared__ __align__(16) float Bs [16*68];
    int tid = threadIdx.x;
    int bm = blockIdx.y * 64;
    int bn = blockIdx.x * 64;
    int ty = tid >> 4, tx = tid & 15;
    int ar = tid >> 2, ac4 = tid & 3;
    int br = tid >> 4, bc4 = tid & 15;
    float acc[4][4] = {};
    for (int kb = 0; kb < 256; kb += 16) {
        float4 av = *(const float4*)(g_hid + (size_t)(bm+ar)*256 + kb + ac4*4);
        Ast[(ac4*4+0)*68 + ar] = av.x;
        Ast[(ac4*4+1)*68 + ar] = av.y;
        Ast[(ac4*4+2)*68 + ar] = av.z;
        Ast[(ac4*4+3)*68 + ar] = av.w;
        *(float4*)&Bs[br*68 + bc4*4] = *(const float4*)(Wout + (size_t)(kb+br)*256 + bn + bc4*4);
        __syncthreads();
#pragma unroll
        for (int k = 0; k < 16; k++) {
            float4 a = *(float4*)&Ast[k*68 + ty*4];
            float4 b = *(float4*)&Bs [k*68 + tx*4];
            acc[0][0]=fmaf(a.x,b.x,acc[0][0]); acc[0][1]=fmaf(a.x,b.y,acc[0][1]);
            acc[0][2]=fmaf(a.x,b.z,acc[0][2]); acc[0][3]=fmaf(a.x,b.w,acc[0][3]);
            acc[1][0]=fmaf(a.y,b.x,acc[1][0]); acc[1][1]=fmaf(a.y,b.y,acc[1][1]);
            acc[1][2]=fmaf(a.y,b.z,acc[1][2]); acc[1][3]=fmaf(a.y,b.w,acc[1][3]);
            acc[2][0]=fmaf(a.z,b.x,acc[2][0]); acc[2][1]=fmaf(a.z,b.y,acc[2][1]);
            acc[2][2]=fmaf(a.z,b.z,acc[2][2]); acc[2][3]=fmaf(a.z,b.w,acc[2][3]);
            acc[3][0]=fmaf(a.w,b.x,acc[3][0]); acc[3][1]=fmaf(a.w,b.y,acc[3][1]);
            acc[3][2]=fmaf(a.w,b.z,acc[3][2]); acc[3][3]=fmaf(a.w,b.w,acc[3][3]);
        }
        __syncthreads();
    }
#pragma unroll
    for (int i = 0; i < 4; i++) {
#pragma unroll
        for (int j = 0; j < 4; j++) {
            int m = bm + ty*4 + i;
            int n = bn + tx*4 + j;
            out[(size_t)m*256 + n] = acc[i][j] + bout[n];
        }
    }
}

// ---------------- launch ----------------
extern "C" void kernel_launch(void* const* d_in, const int* in_sizes, int n_in,
                              void* d_out, int out_size) {
    const float* x       = (const float*)d_in[0];
    const float* bias    = (const float*)d_in[1];
    const float* g_gamma = (const float*)d_in[2];
    const float* g_beta  = (const float*)d_in[3];
    const float* b_gamma = (const float*)d_in[4];
    const float* b_beta  = (const float*)d_in[5];
    const float* Wq      = (const float*)d_in[6];
    const float* Wk      = (const float*)d_in[7];
    const float* Wv      = (const float*)d_in[8];
    const float* Wb      = (const float*)d_in[9];
    const float* Wg      = (const float*)d_in[10];
    const float* bg      = (const float*)d_in[11];
    const float* Wout    = (const float*)d_in[12];
    const float* bout    = (const float*)d_in[13];
    float* out = (float*)d_out;

    prep_wb<<<1, 128>>>(b_gamma, b_beta, Wb);
    ln_x<<<256, 128>>>(x, g_gamma, g_beta);
    gemm_qkvg<<<dim3(16, 16), 256>>>(Wq, Wk, Wv, Wg, bg);
    pair_ln<<<16384, 256>>>(bias);
    attn_kernel<<<256, 128>>>();
    gemm_out<<<dim3(4, 16), 256>>>(Wout, bout, out);
}

// round 4
// speedup vs baseline: 1.8849x; 1.8849x over previous
#include <cuda_runtime.h>
#include <math.h>

#define LSEQ 512
#define BATCH 2
#define DG 256
#define DB 128
#define NH 8
#define HD 32
#define BH (BATCH*NH)   // 16

// ---------------- scratch (device globals; no allocation allowed) ----------------
__device__ float g_xn[BATCH*LSEQ*DG];        // LN(x)                [1024][256]
__device__ float g_q[BH*LSEQ*HD];            // [b*h][l][32]
__device__ float g_k[BH*LSEQ*HD];            // pre-scaled by 1/sqrt(32)
__device__ float g_v[BH*LSEQ*HD];
__device__ float g_gate[BATCH*LSEQ*DG];      // sigmoid(xn@Wg+bg)    [1024][256]
__device__ float g_pb[(size_t)BH*LSEQ*LSEQ]; // pair bias            [b*h][q][k]
__device__ float g_hid[BATCH*LSEQ*DG];       // gate * attn_out      [1024][256]
__device__ float g_wgt[NH*DB];               // b_gamma[i]*Wb[i][h]  [h][i]
__device__ float g_cw[NH];                   // sum_i b_gamma[i]*Wb[i][h]
__device__ float g_bb[NH];                   // b_beta @ Wb[:,h]

// packed f32x2 helpers (sm_10x FFMA2 path — PTX only)
__device__ __forceinline__ void ffma2(unsigned long long& acc,
                                      unsigned long long a,
                                      unsigned long long b) {
    asm("fma.rn.f32x2 %0, %1, %2, %0;" : "+l"(acc) : "l"(a), "l"(b));
}
__device__ __forceinline__ void fadd2(unsigned long long& acc, unsigned long long a) {
    asm("add.rn.f32x2 %0, %1, %0;" : "+l"(acc) : "l"(a));
}
__device__ __forceinline__ float2 unpack2(unsigned long long v) {
    float2 r;
    asm("mov.b64 {%0, %1}, %2;" : "=f"(r.x), "=f"(r.y) : "l"(v));
    return r;
}

// ---------------- prep: fold b_gamma/b_beta into Wb ----------------
__global__ void prep_wb(const float* __restrict__ b_gamma,
                        const float* __restrict__ b_beta,
                        const float* __restrict__ Wb) {
    __shared__ float sc[NH][DB];
    __shared__ float sb[NH][DB];
    int i = threadIdx.x;            // 128 threads
    float g = b_gamma[i];
    float bt = b_beta[i];
#pragma unroll
    for (int h = 0; h < NH; h++) {
        float w = Wb[i*NH + h];
        g_wgt[h*DB + i] = g * w;
        sc[h][i] = g * w;
        sb[h][i] = bt * w;
    }
    __syncthreads();
    if (i < NH) {
        float a = 0.f, b2 = 0.f;
        for (int j = 0; j < DB; j++) { a += sc[i][j]; b2 += sb[i][j]; }
        g_cw[i] = a;
        g_bb[i] = b2;
    }
}

// ---------------- LN over x rows (dim 256), warp per row ----------------
__global__ void __launch_bounds__(128) ln_x(const float* __restrict__ x,
                                            const float* __restrict__ gamma,
                                            const float* __restrict__ beta) {
    int warp = threadIdx.x >> 5, lane = threadIdx.x & 31;
    int row = blockIdx.x * 4 + warp;           // 1024 rows, grid 256
    const float* rp = x + (size_t)row * DG;
    float4 v0 = *(const float4*)(rp + lane*4);
    float4 v1 = *(const float4*)(rp + 128 + lane*4);
    float s1 = v0.x+v0.y+v0.z+v0.w + v1.x+v1.y+v1.z+v1.w;
    float s2 = v0.x*v0.x+v0.y*v0.y+v0.z*v0.z+v0.w*v0.w
             + v1.x*v1.x+v1.y*v1.y+v1.z*v1.z+v1.w*v1.w;
#pragma unroll
    for (int off = 16; off; off >>= 1) {
        s1 += __shfl_xor_sync(0xffffffffu, s1, off);
        s2 += __shfl_xor_sync(0xffffffffu, s2, off);
    }
    float mu = s1 * (1.f/256.f);
    float var = s2 * (1.f/256.f) - mu*mu;
    float rstd = rsqrtf(var + 1e-5f);
    float4 gm0 = *(const float4*)(gamma + lane*4);
    float4 gm1 = *(const float4*)(gamma + 128 + lane*4);
    float4 bt0 = *(const float4*)(beta + lane*4);
    float4 bt1 = *(const float4*)(beta + 128 + lane*4);
    float4 o0, o1;
    o0.x = (v0.x-mu)*rstd*gm0.x + bt0.x; o0.y = (v0.y-mu)*rstd*gm0.y + bt0.y;
    o0.z = (v0.z-mu)*rstd*gm0.z + bt0.z; o0.w = (v0.w-mu)*rstd*gm0.w + bt0.w;
    o1.x = (v1.x-mu)*rstd*gm1.x + bt1.x; o1.y = (v1.y-mu)*rstd*gm1.y + bt1.y;
    o1.z = (v1.z-mu)*rstd*gm1.z + bt1.z; o1.w = (v1.w-mu)*rstd*gm1.w + bt1.w;
    *(float4*)(g_xn + (size_t)row*DG + lane*4) = o0;
    *(float4*)(g_xn + (size_t)row*DG + 128 + lane*4) = o1;
}

// ---------------- fused GEMM: xn @ [Wq|Wk|Wv|Wg] (M=1024, N=1024, K=256) ----------------
__global__ void __launch_bounds__(256) gemm_qkvg(const float* __restrict__ Wq,
                                                 const float* __restrict__ Wk,
                                                 const float* __restrict__ Wv,
                                                 const float* __restrict__ Wg,
                                                 const float* __restrict__ bg) {
    __shared__ __align__(16) float Ast[16*68];   // [k][m] transposed, padded
    __shared__ __align__(16) float Bs [16*68];   // [k][n], padded
    int tid = threadIdx.x;
    int bm = blockIdx.y * 64;
    int bn_g = blockIdx.x * 64;          // 0..1023
    int which = bn_g >> 8;               // 0:Q 1:K 2:V 3:G
    int bn = bn_g & 255;
    const float* W = (which==0) ? Wq : (which==1) ? Wk : (which==2) ? Wv : Wg;
    int ty = tid >> 4, tx = tid & 15;
    int ar = tid >> 2, ac4 = tid & 3;
    int br = tid >> 4, bc4 = tid & 15;
    float acc[4][4] = {};
    for (int kb = 0; kb < 256; kb += 16) {
        float4 av = *(const float4*)(g_xn + (size_t)(bm+ar)*256 + kb + ac4*4);
        Ast[(ac4*4+0)*68 + ar] = av.x;
        Ast[(ac4*4+1)*68 + ar] = av.y;
        Ast[(ac4*4+2)*68 + ar] = av.z;
        Ast[(ac4*4+3)*68 + ar] = av.w;
        *(float4*)&Bs[br*68 + bc4*4] = *(const float4*)(W + (size_t)(kb+br)*256 + bn + bc4*4);
        __syncthreads();
#pragma unroll
        for (int k = 0; k < 16; k++) {
            float4 a = *(float4*)&Ast[k*68 + ty*4];
            float4 b = *(float4*)&Bs [k*68 + tx*4];
            acc[0][0]=fmaf(a.x,b.x,acc[0][0]); acc[0][1]=fmaf(a.x,b.y,acc[0][1]);
            acc[0][2]=fmaf(a.x,b.z,acc[0][2]); acc[0][3]=fmaf(a.x,b.w,acc[0][3]);
            acc[1][0]=fmaf(a.y,b.x,acc[1][0]); acc[1][1]=fmaf(a.y,b.y,acc[1][1]);
            acc[1][2]=fmaf(a.y,b.z,acc[1][2]); acc[1][3]=fmaf(a.y,b.w,acc[1][3]);
            acc[2][0]=fmaf(a.z,b.x,acc[2][0]); acc[2][1]=fmaf(a.z,b.y,acc[2][1]);
            acc[2][2]=fmaf(a.z,b.z,acc[2][2]); acc[2][3]=fmaf(a.z,b.w,acc[2][3]);
            acc[3][0]=fmaf(a.w,b.x,acc[3][0]); acc[3][1]=fmaf(a.w,b.y,acc[3][1]);
            acc[3][2]=fmaf(a.w,b.z,acc[3][2]); acc[3][3]=fmaf(a.w,b.w,acc[3][3]);
        }
        __syncthreads();
    }
    const float kscale = 0.17677669529663687f; // 1/sqrt(32)
#pragma unroll
    for (int i = 0; i < 4; i++) {
#pragma unroll
        for (int j = 0; j < 4; j++) {
            int m = bm + ty*4 + i;
            int n = bn + tx*4 + j;
            float v = acc[i][j];
            if (which < 3) {
                if (which == 1) v *= kscale;
                int b = m >> 9, pos = m & 511, h = n >> 5, d = n & 31;
                float* dst = (which==0) ? g_q : (which==1) ? g_k : g_v;
                dst[((size_t)(b*NH + h)*LSEQ + pos)*HD + d] = v;
            } else {
                v = 1.f / (1.f + __expf(-(v + bg[n])));
                g_gate[(size_t)m*DG + n] = v;
            }
        }
    }
}

// ---------------- fused LN(bias) @ Wb -> pair bias in [b,h,q,k] ----------------
// Redesigned: lane li owns the CONTIGUOUS 16B chunk at byte j*128 + li*16
//   -> LDG: each instruction covers 4 full 128B lines (warp reads 2KB contiguous)
//   -> LDS: weight reads are 8 contiguous 16B chunks (128B), broadcast across subs
//      (conflict-free, single phase)
//   -> dots use packed fma.rn.f32x2 (half the FMA instruction count)
__global__ void __launch_bounds__(256) pair_ln(const float* __restrict__ bias) {
    __shared__ __align__(16) float swg[NH*DB];
    __shared__ float scw[NH], sbb[NH];
    int tid = threadIdx.x;
    for (int i = tid; i < NH*DB; i += 256) swg[i] = g_wgt[i];
    if (tid < NH) { scw[tid] = g_cw[tid]; sbb[tid] = g_bb[tid]; }
    __syncthreads();
    int warp = tid >> 5, lane = tid & 31;
    int sub = lane >> 3, li = lane & 7;
    unsigned row = blockIdx.x * 32u + warp * 4u + sub;   // < 524288
    const ulonglong2* rp = (const ulonglong2*)(bias + (size_t)row * DB);

    // load this lane's 16 elements: chunks j=0..3 at u128 index j*8 + li
    unsigned long long xv[8];
#pragma unroll
    for (int j = 0; j < 4; j++) {
        ulonglong2 t = rp[j*8 + li];
        xv[2*j]   = t.x;
        xv[2*j+1] = t.y;
    }

    // stats (packed)
    unsigned long long s1p = 0ull, s2p = 0ull;
#pragma unroll
    for (int j = 0; j < 8; j++) {
        fadd2(s1p, xv[j]);
        ffma2(s2p, xv[j], xv[j]);
    }

    // 8 dot products vs folded weights
    const ulonglong2* wsp = (const ulonglong2*)swg;  // index: h*32 + j*8 + li
    unsigned long long acc[NH];
#pragma unroll
    for (int h = 0; h < NH; h++) {
        unsigned long long a = 0ull;
#pragma unroll
        for (int j = 0; j < 4; j++) {
            ulonglong2 w = wsp[h*32 + j*8 + li];
            ffma2(a, xv[2*j],   w.x);
            ffma2(a, xv[2*j+1], w.y);
        }
        acc[h] = a;
    }

    float2 t1 = unpack2(s1p);
    float2 t2 = unpack2(s2p);
    float s1 = t1.x + t1.y;
    float s2 = t2.x + t2.y;
    float d[NH];
#pragma unroll
    for (int h = 0; h < NH; h++) {
        float2 td = unpack2(acc[h]);
        d[h] = td.x + td.y;
    }

    // reduce across the 8 lanes of this row
#pragma unroll
    for (int off = 4; off; off >>= 1) {
        s1 += __shfl_xor_sync(0xffffffffu, s1, off);
        s2 += __shfl_xor_sync(0xffffffffu, s2, off);
#pragma unroll
        for (int h = 0; h < NH; h++) d[h] += __shfl_xor_sync(0xffffffffu, d[h], off);
    }

    float mu = s1 * (1.f/128.f);
    float var = s2 * (1.f/128.f) - mu*mu;
    float rstd = rsqrtf(var + 1e-5f);

    // lane li emits head h = li (static-index select; all lanes hold full sums)
    float dh = d[0];
#pragma unroll
    for (int h = 1; h < NH; h++) dh = (li == h) ? d[h] : dh;

    float val = fmaf(rstd, dh - mu*scw[li], sbb[li]);
    unsigned b = row >> 18, q = (row >> 9) & 511u, k = row & 511u;
    g_pb[(((size_t)(b*NH + li)*LSEQ + q))*LSEQ + k] = val;
}

// ---------------- flash-style attention + gate ----------------
// block: 128 threads, 32 q rows; thread = (ty 0..15: 2 q rows, tx 0..7: k lanes / 4 d cols)
__global__ void __launch_bounds__(128) attn_kernel() {
    __shared__ __align__(16) float Qs[32*36];
    __shared__ __align__(16) float Ks[64*36];
    __shared__ __align__(16) float Vs[64*32];
    __shared__ __align__(16) float Ps[32*64];
    int tid = threadIdx.x;
    int bh = blockIdx.x >> 4;
    int q0 = (blockIdx.x & 15) * 32;
    const float* Qg = g_q + (size_t)bh * LSEQ * HD;
    const float* Kg = g_k + (size_t)bh * LSEQ * HD;
    const float* Vg = g_v + (size_t)bh * LSEQ * HD;
    for (int i = tid; i < 256; i += 128) {
        int r = i >> 3, c = i & 7;
        *(float4*)&Qs[r*36 + c*4] = *(const float4*)(Qg + (size_t)(q0+r)*HD + c*4);
    }
    int ty = tid >> 3, tx = tid & 7;
    int qa = q0 + 2*ty;
    const float* pb0 = g_pb + ((size_t)bh * LSEQ + qa) * LSEQ;
    const float* pb1 = pb0 + LSEQ;
    float m0 = __int_as_float(0xff800000u), m1 = m0;
    float l0 = 0.f, l1 = 0.f;
    float c0[4] = {0,0,0,0}, c1[4] = {0,0,0,0};

    for (int kt = 0; kt < LSEQ; kt += 64) {
        __syncthreads();
        for (int i = tid; i < 512; i += 128) {
            int r = i >> 3, c = i & 7;
            *(float4*)&Ks[r*36 + c*4] = *(const float4*)(Kg + (size_t)(kt+r)*HD + c*4);
        }
        for (int i = tid; i < 512; i += 128) {
            int r = i >> 3, c = i & 7;
            *(float4*)&Vs[r*32 + c*4] = *(const float4*)(Vg + (size_t)(kt+r)*HD + c*4);
        }
        __syncthreads();
        // logits: s[j] for k = kt + tx + 8j  (interleaved -> conflict-free Ks reads)
        float s0[8], s1v[8];
#pragma unroll
        for (int j = 0; j < 8; j++) {
            s0[j]  = pb0[kt + tx + 8*j];
            s1v[j] = pb1[kt + tx + 8*j];
        }
#pragma unroll
        for (int d4 = 0; d4 < 8; d4++) {
            float4 a0 = *(float4*)&Qs[(2*ty  )*36 + d4*4];
            float4 a1 = *(float4*)&Qs[(2*ty+1)*36 + d4*4];
#pragma unroll
            for (int j = 0; j < 8; j++) {
                float4 kv = *(float4*)&Ks[(tx + 8*j)*36 + d4*4];
                s0[j]  = fmaf(a0.x,kv.x, fmaf(a0.y,kv.y, fmaf(a0.z,kv.z, fmaf(a0.w,kv.w, s0[j]))));
                s1v[j] = fmaf(a1.x,kv.x, fmaf(a1.y,kv.y, fmaf(a1.z,kv.z, fmaf(a1.w,kv.w, s1v[j]))));
            }
        }
        // online softmax across the 8-lane group
        float mx0 = s0[0], mx1 = s1v[0];
#pragma unroll
        for (int j = 1; j < 8; j++) { mx0 = fmaxf(mx0, s0[j]); mx1 = fmaxf(mx1, s1v[j]); }
#pragma unroll
        for (int off = 4; off; off >>= 1) {
            mx0 = fmaxf(mx0, __shfl_xor_sync(0xffffffffu, mx0, off));
            mx1 = fmaxf(mx1, __shfl_xor_sync(0xffffffffu, mx1, off));
        }
        float mn0 = fmaxf(m0, mx0), mn1 = fmaxf(m1, mx1);
        float sc0 = __expf(m0 - mn0), sc1 = __expf(m1 - mn1);
        float sum0 = 0.f, sum1 = 0.f;
#pragma unroll
        for (int j = 0; j < 8; j++) {
            s0[j]  = __expf(s0[j]  - mn0); sum0 += s0[j];
            s1v[j] = __expf(s1v[j] - mn1); sum1 += s1v[j];
        }
#pragma unroll
        for (int off = 4; off; off >>= 1) {
            sum0 += __shfl_xor_sync(0xffffffffu, sum0, off);
            sum1 += __shfl_xor_sync(0xffffffffu, sum1, off);
        }
        l0 = l0*sc0 + sum0; l1 = l1*sc1 + sum1;
        m0 = mn0; m1 = mn1;
#pragma unroll
        for (int j = 0; j < 4; j++) { c0[j] *= sc0; c1[j] *= sc1; }
#pragma unroll
        for (int j = 0; j < 8; j++) {
            Ps[(2*ty  )*64 + tx + 8*j] = s0[j];
            Ps[(2*ty+1)*64 + tx + 8*j] = s1v[j];
        }
        __syncthreads();
        // O += P @ V  (thread: 2 q rows x 4 d cols, d = tx*4..+3)
#pragma unroll
        for (int k4 = 0; k4 < 16; k4++) {
            float4 pa = *(float4*)&Ps[(2*ty  )*64 + k4*4];
            float4 pb_ = *(float4*)&Ps[(2*ty+1)*64 + k4*4];
            float4 va = *(float4*)&Vs[(k4*4+0)*32 + tx*4];
            float4 vb = *(float4*)&Vs[(k4*4+1)*32 + tx*4];
            float4 vc = *(float4*)&Vs[(k4*4+2)*32 + tx*4];
            float4 vd = *(float4*)&Vs[(k4*4+3)*32 + tx*4];
            c0[0]=fmaf(pa.x,va.x,c0[0]); c0[1]=fmaf(pa.x,va.y,c0[1]); c0[2]=fmaf(pa.x,va.z,c0[2]); c0[3]=fmaf(pa.x,va.w,c0[3]);
            c1[0]=fmaf(pb_.x,va.x,c1[0]); c1[1]=fmaf(pb_.x,va.y,c1[1]); c1[2]=fmaf(pb_.x,va.z,c1[2]); c1[3]=fmaf(pb_.x,va.w,c1[3]);
            c0[0]=fmaf(pa.y,vb.x,c0[0]); c0[1]=fmaf(pa.y,vb.y,c0[1]); c0[2]=fmaf(pa.y,vb.z,c0[2]); c0[3]=fmaf(pa.y,vb.w,c0[3]);
            c1[0]=fmaf(pb_.y,vb.x,c1[0]); c1[1]=fmaf(pb_.y,vb.y,c1[1]); c1[2]=fmaf(pb_.y,vb.z,c1[2]); c1[3]=fmaf(pb_.y,vb.w,c1[3]);
            c0[0]=fmaf(pa.z,vc.x,c0[0]); c0[1]=fmaf(pa.z,vc.y,c0[1]); c0[2]=fmaf(pa.z,vc.z,c0[2]); c0[3]=fmaf(pa.z,vc.w,c0[3]);
            c1[0]=fmaf(pb_.z,vc.x,c1[0]); c1[1]=fmaf(pb_.z,vc.y,c1[1]); c1[2]=fmaf(pb_.z,vc.z,c1[2]); c1[3]=fmaf(pb_.z,vc.w,c1[3]);
            c0[0]=fmaf(pa.w,vd.x,c0[0]); c0[1]=fmaf(pa.w,vd.y,c0[1]); c0[2]=fmaf(pa.w,vd.z,c0[2]); c0[3]=fmaf(pa.w,vd.w,c0[3]);
            c1[0]=fmaf(pb_.w,vd.x,c1[0]); c1[1]=fmaf(pb_.w,vd.y,c1[1]); c1[2]=fmaf(pb_.w,vd.z,c1[2]); c1[3]=fmaf(pb_.w,vd.w,c1[3]);
        }
    }
    float inv0 = 1.f / l0, inv1 = 1.f / l1;
    int b = bh >> 3, h = bh & 7;
    int mrow = b * LSEQ + qa;
    const float* gt = g_gate + (size_t)mrow * DG + h*HD + tx*4;
    float4 gA = *(const float4*)gt;
    float4 gB = *(const float4*)(gt + DG);
    float4 oA = make_float4(c0[0]*inv0*gA.x, c0[1]*inv0*gA.y, c0[2]*inv0*gA.z, c0[3]*inv0*gA.w);
    float4 oB = make_float4(c1[0]*inv1*gB.x, c1[1]*inv1*gB.y, c1[2]*inv1*gB.z, c1[3]*inv1*gB.w);
    *(float4*)(g_hid + (size_t)mrow*DG + h*HD + tx*4) = oA;
    *(float4*)(g_hid + (size_t)(mrow+1)*DG + h*HD + tx*4) = oB;
}

// ---------------- final GEMM: hid @ Wout + bout ----------------
__global__ void __launch_bounds__(256) gemm_out(const float* __restrict__ Wout,
                                                const float* __restrict__ bout,
                                                float* __restrict__ out) {
    __shared__ __align__(16) float Ast[16*68];
    __shared__ __align__(16) float Bs [16*68];
    int tid = threadIdx.x;
    int bm = blockIdx.y * 64;
    int bn = blockIdx.x * 64;
    int ty = tid >> 4, tx = tid & 15;
    int ar = tid >> 2, ac4 = tid & 3;
    int br = tid >> 4, bc4 = tid & 15;
    float acc[4][4] = {};
    for (int kb = 0; kb < 256; kb += 16) {
        float4 av = *(const float4*)(g_hid + (size_t)(bm+ar)*256 + kb + ac4*4);
        Ast[(ac4*4+0)*68 + ar] = av.x;
        Ast[(ac4*4+1)*68 + ar] = av.y;
        Ast[(ac4*4+2)*68 + ar] = av.z;
        Ast[(ac4*4+3)*68 + ar] = av.w;
        *(float4*)&Bs[br*68 + bc4*4] = *(const float4*)(Wout + (size_t)(kb+br)*256 + bn + bc4*4);
        __syncthreads();
#pragma unroll
        for (int k = 0; k < 16; k++) {
            float4 a = *(float4*)&Ast[k*68 + ty*4];
            float4 b = *(float4*)&Bs [k*68 + tx*4];
            acc[0][0]=fmaf(a.x,b.x,acc[0][0]); acc[0][1]=fmaf(a.x,b.y,acc[0][1]);
            acc[0][2]=fmaf(a.x,b.z,acc[0][2]); acc[0][3]=fmaf(a.x,b.w,acc[0][3]);
            acc[1][0]=fmaf(a.y,b.x,acc[1][0]); acc[1][1]=fmaf(a.y,b.y,acc[1][1]);
            acc[1][2]=fmaf(a.y,b.z,acc[1][2]); acc[1][3]=fmaf(a.y,b.w,acc[1][3]);
            acc[2][0]=fmaf(a.z,b.x,acc[2][0]); acc[2][1]=fmaf(a.z,b.y,acc[2][1]);
            acc[2][2]=fmaf(a.z,b.z,acc[2][2]); acc[2][3]=fmaf(a.z,b.w,acc[2][3]);
            acc[3][0]=fmaf(a.w,b.x,acc[3][0]); acc[3][1]=fmaf(a.w,b.y,acc[3][1]);
            acc[3][2]=fmaf(a.w,b.z,acc[3][2]); acc[3][3]=fmaf(a.w,b.w,acc[3][3]);
        }
        __syncthreads();
    }
#pragma unroll
    for (int i = 0; i < 4; i++) {
#pragma unroll
        for (int j = 0; j < 4; j++) {
            int m = bm + ty*4 + i;
            int n = bn + tx*4 + j;
            out[(size_t)m*256 + n] = acc[i][j] + bout[n];
        }
    }
}

// ---------------- launch ----------------
extern "C" void kernel_launch(void* const* d_in, const int* in_sizes, int n_in,
                              void* d_out, int out_size) {
    const float* x       = (const float*)d_in[0];
    const float* bias    = (const float*)d_in[1];
    const float* g_gamma = (const float*)d_in[2];
    const float* g_beta  = (const float*)d_in[3];
    const float* b_gamma = (const float*)d_in[4];
    const float* b_beta  = (const float*)d_in[5];
    const float* Wq      = (const float*)d_in[6];
    const float* Wk      = (const float*)d_in[7];
    const float* Wv      = (const float*)d_in[8];
    const float* Wb      = (const float*)d_in[9];
    const float* Wg      = (const float*)d_in[10];
    const float* bg      = (const float*)d_in[11];
    const float* Wout    = (const float*)d_in[12];
    const float* bout    = (const float*)d_in[13];
    float* out = (float*)d_out;

    prep_wb<<<1, 128>>>(b_gamma, b_beta, Wb);
    ln_x<<<256, 128>>>(x, g_gamma, g_beta);
    gemm_qkvg<<<dim3(16, 16), 256>>>(Wq, Wk, Wv, Wg, bg);
    pair_ln<<<16384, 256>>>(bias);
    attn_kernel<<<256, 128>>>();
    gemm_out<<<dim3(4, 16), 256>>>(Wout, bout, out);
}